// round 3
// baseline (speedup 1.0000x reference)
#include <cuda_runtime.h>

// CoupledCLEFOModel: y = ((1+eps)I - Gamma - diag(Lambda@x))^{-1} (Ups + B@x + Theta@z)
// Jacobi splitting: y_{k+1} = D^{-1} rhs + D^{-1} (Gamma y_k), 9 iters -> ~1e-7.
// One thread per sample. R3: register-pressure fix — launch_bounds(128,3) (170-reg cap),
// rolled outer loops, explicit LDS.128 broadcast reads. Goal: zero spills.

#define NDEP  32
#define NIND  64
#define NINT  16
#define TPB   128
#define NITER 9
#define REGC  1e-7f

__global__ __launch_bounds__(TPB, 3)
void clefo_kernel(const float* __restrict__ X,
                  const float* __restrict__ Z,
                  const float* __restrict__ Ups,
                  const float* __restrict__ Bm,
                  const float* __restrict__ Th,
                  const float* __restrict__ Gm,
                  const float* __restrict__ Lm,
                  float* __restrict__ out,
                  int batch)
{
    // Transposed parameter matrices; rows of 32 floats = 8 float4 (128B, LDS.128-friendly).
    __shared__ __align__(16) float sBt[NIND][NDEP];   // sBt[j][i] = B[i][j]
    __shared__ __align__(16) float sLt[NIND][NDEP];   // sLt[j][i] = Lambda[i][j]
    __shared__ __align__(16) float sTt[NINT][NDEP];   // sTt[k][i] = Theta[i][k]
    __shared__ __align__(16) float sGt[NDEP][NDEP];   // sGt[j][i] = Gamma[i][j]
    __shared__ __align__(16) float sU[NDEP];

    const int tid = threadIdx.x;

    for (int idx = tid; idx < NDEP * NIND; idx += TPB) {
        int i = idx / NIND, j = idx % NIND;
        sBt[j][i] = Bm[idx];
        sLt[j][i] = Lm[idx];
    }
    for (int idx = tid; idx < NDEP * NINT; idx += TPB) {
        int i = idx / NINT, k = idx % NINT;
        sTt[k][i] = Th[idx];
    }
    for (int idx = tid; idx < NDEP * NDEP; idx += TPB) {
        int i = idx / NDEP, j = idx % NDEP;
        sGt[j][i] = Gm[idx];
    }
    if (tid < NDEP) sU[tid] = Ups[tid];
    __syncthreads();

    const int s = blockIdx.x * TPB + tid;
    if (s >= batch) return;

    float rhs[NDEP], lam[NDEP];
#pragma unroll
    for (int i = 0; i < NDEP; i++) { rhs[i] = sU[i]; lam[i] = 0.0f; }

    // ---- Phase 1: rhs += B@x, lam = Lambda@x. Outer loop rolled; x scalar per step.
    const float* Xs = X + (size_t)s * NIND;
    for (int j = 0; j < NIND; j++) {
        float xj = __ldg(&Xs[j]);
        const float4* b4 = reinterpret_cast<const float4*>(&sBt[j][0]);
        const float4* l4 = reinterpret_cast<const float4*>(&sLt[j][0]);
#pragma unroll
        for (int q = 0; q < NDEP / 4; q++) {
            float4 bv = b4[q];
            float4 lv = l4[q];
            rhs[4*q+0] = fmaf(bv.x, xj, rhs[4*q+0]);
            rhs[4*q+1] = fmaf(bv.y, xj, rhs[4*q+1]);
            rhs[4*q+2] = fmaf(bv.z, xj, rhs[4*q+2]);
            rhs[4*q+3] = fmaf(bv.w, xj, rhs[4*q+3]);
            lam[4*q+0] = fmaf(lv.x, xj, lam[4*q+0]);
            lam[4*q+1] = fmaf(lv.y, xj, lam[4*q+1]);
            lam[4*q+2] = fmaf(lv.z, xj, lam[4*q+2]);
            lam[4*q+3] = fmaf(lv.w, xj, lam[4*q+3]);
        }
    }

    // ---- rhs += Theta@z
    const float* Zs = Z + (size_t)s * NINT;
    for (int k = 0; k < NINT; k++) {
        float zk = __ldg(&Zs[k]);
        const float4* t4 = reinterpret_cast<const float4*>(&sTt[k][0]);
#pragma unroll
        for (int q = 0; q < NDEP / 4; q++) {
            float4 tv = t4[q];
            rhs[4*q+0] = fmaf(tv.x, zk, rhs[4*q+0]);
            rhs[4*q+1] = fmaf(tv.y, zk, rhs[4*q+1]);
            rhs[4*q+2] = fmaf(tv.z, zk, rhs[4*q+2]);
            rhs[4*q+3] = fmaf(tv.w, zk, rhs[4*q+3]);
        }
    }

    // ---- Phase 2: dinv = 1/(1+eps - lam); rhs <- D^{-1} rhs; y0 = rhs
    // lam[] dies here; dinv reuses its registers.
    float dinv[NDEP], y[NDEP];
#pragma unroll
    for (int i = 0; i < NDEP; i++) {
        dinv[i] = 1.0f / ((1.0f + REGC) - lam[i]);
        rhs[i] *= dinv[i];
        y[i] = rhs[i];
    }

    // ---- Phase 3: Jacobi iterations  y = rhs + dinv .* (Gamma @ y)  (it-loop rolled)
    for (int it = 0; it < NITER; it++) {
        float acc[NDEP];
#pragma unroll
        for (int i = 0; i < NDEP; i++) acc[i] = 0.0f;
#pragma unroll
        for (int j = 0; j < NDEP; j++) {
            float yj = y[j];
            const float4* g4 = reinterpret_cast<const float4*>(&sGt[j][0]);
#pragma unroll
            for (int q = 0; q < NDEP / 4; q++) {
                float4 gv = g4[q];
                acc[4*q+0] = fmaf(gv.x, yj, acc[4*q+0]);
                acc[4*q+1] = fmaf(gv.y, yj, acc[4*q+1]);
                acc[4*q+2] = fmaf(gv.z, yj, acc[4*q+2]);
                acc[4*q+3] = fmaf(gv.w, yj, acc[4*q+3]);
            }
        }
#pragma unroll
        for (int i = 0; i < NDEP; i++) y[i] = fmaf(dinv[i], acc[i], rhs[i]);
    }

    // ---- Write out
    float4* O4 = reinterpret_cast<float4*>(out + (size_t)s * NDEP);
#pragma unroll
    for (int c = 0; c < NDEP / 4; c++) {
        O4[c] = make_float4(y[4 * c + 0], y[4 * c + 1], y[4 * c + 2], y[4 * c + 3]);
    }
}

extern "C" void kernel_launch(void* const* d_in, const int* in_sizes, int n_in,
                              void* d_out, int out_size)
{
    const float* X   = (const float*)d_in[0];  // [batch, 64]
    const float* Z   = (const float*)d_in[1];  // [batch, 16]
    const float* Ups = (const float*)d_in[2];  // [32, 1]
    const float* Bm  = (const float*)d_in[3];  // [32, 64]
    const float* Th  = (const float*)d_in[4];  // [32, 16]
    const float* Gm  = (const float*)d_in[5];  // [32, 32]
    const float* Lm  = (const float*)d_in[6];  // [32, 64]
    float* out = (float*)d_out;

    int batch = in_sizes[0] / NIND;
    int nblocks = (batch + TPB - 1) / TPB;
    clefo_kernel<<<nblocks, TPB>>>(X, Z, Ups, Bm, Th, Gm, Lm, out, batch);
}

// round 4
// speedup vs baseline: 6.2241x; 6.2241x over previous
#include <cuda_runtime.h>

// CoupledCLEFOModel: y = ((1+eps)I - Gamma - diag(Lambda@x))^{-1} (Ups + B@x + Theta@z)
// Jacobi: y_{k+1} = D^{-1}rhs + D^{-1}(Gamma y_k), 8 iters (~1.5e-6).
// R4: TWO THREADS PER SAMPLE (lane pair h=tid&1 owns rows [16h,16h+16)).
// Live regs ~100 -> no spills under 128-reg cap. X/Z staged in padded SMEM.

#define NDEP  32
#define HALF  16
#define NIND  64
#define NINT  16
#define TPB   128
#define SPB   (TPB / 2)      // 64 samples per block
#define NITER 8
#define REGC  1e-7f

__global__ __launch_bounds__(TPB, 4)
void clefo_kernel(const float* __restrict__ X,
                  const float* __restrict__ Z,
                  const float* __restrict__ Ups,
                  const float* __restrict__ Bm,
                  const float* __restrict__ Th,
                  const float* __restrict__ Gm,
                  const float* __restrict__ Lm,
                  float* __restrict__ out,
                  int batch)
{
    __shared__ __align__(16) float sBt[NIND][NDEP];   // sBt[j][i] = B[i][j]
    __shared__ __align__(16) float sLt[NIND][NDEP];   // sLt[j][i] = Lambda[i][j]
    __shared__ __align__(16) float sTt[NINT][NDEP];   // sTt[k][i] = Theta[i][k]
    __shared__ __align__(16) float sGt[NDEP][NDEP];   // sGt[j][i] = Gamma[i][j]
    __shared__            float sU[NDEP];
    __shared__            float sX[SPB][NIND + 1];    // padded: bank-conflict-free
    __shared__            float sZ[SPB][NINT + 1];

    const int tid = threadIdx.x;

    // ---- Stage parameter matrices (transposed) ----
    for (int idx = tid; idx < NDEP * NIND; idx += TPB) {
        int i = idx / NIND, j = idx % NIND;
        sBt[j][i] = Bm[idx];
        sLt[j][i] = Lm[idx];
    }
    for (int idx = tid; idx < NDEP * NINT; idx += TPB) {
        int i = idx / NINT, k = idx % NINT;
        sTt[k][i] = Th[idx];
    }
    for (int idx = tid; idx < NDEP * NDEP; idx += TPB) {
        int i = idx / NDEP, j = idx % NDEP;
        sGt[j][i] = Gm[idx];
    }
    if (tid < NDEP) sU[tid] = Ups[tid];

    // ---- Stage X / Z for this block's samples (coalesced float4 reads) ----
    const int sbase = blockIdx.x * SPB;
    const int nsamp = min(SPB, batch - sbase);          // = SPB for 65536
    {
        const float4* Xg = reinterpret_cast<const float4*>(X + (size_t)sbase * NIND);
        int nf4 = nsamp * (NIND / 4);
        for (int idx = tid; idx < nf4; idx += TPB) {
            float4 v = Xg[idx];
            int ls = idx >> 4;                // 16 float4 per sample
            int j4 = (idx & 15) << 2;
            sX[ls][j4 + 0] = v.x; sX[ls][j4 + 1] = v.y;
            sX[ls][j4 + 2] = v.z; sX[ls][j4 + 3] = v.w;
        }
        const float4* Zg = reinterpret_cast<const float4*>(Z + (size_t)sbase * NINT);
        int nz4 = nsamp * (NINT / 4);
        for (int idx = tid; idx < nz4; idx += TPB) {
            float4 v = Zg[idx];
            int ls = idx >> 2;                // 4 float4 per sample
            int k4 = (idx & 3) << 2;
            sZ[ls][k4 + 0] = v.x; sZ[ls][k4 + 1] = v.y;
            sZ[ls][k4 + 2] = v.z; sZ[ls][k4 + 3] = v.w;
        }
    }
    __syncthreads();

    const int ls = tid >> 1;                  // local sample
    const int h  = tid & 1;                   // which half of the rows
    const int rb = h * HALF;                  // row base
    const int s  = sbase + ls;
    if (ls >= nsamp) return;

    // ---- Phase 1: rhs = Ups + B@x + Theta@z (own rows), lam = Lambda@x ----
    float rhs[HALF], lam[HALF];
#pragma unroll
    for (int r = 0; r < HALF; r++) { rhs[r] = sU[rb + r]; lam[r] = 0.0f; }

    for (int j = 0; j < NIND; j++) {
        float xj = sX[ls][j];
        const float4* b4 = reinterpret_cast<const float4*>(&sBt[j][rb]);
        const float4* l4 = reinterpret_cast<const float4*>(&sLt[j][rb]);
#pragma unroll
        for (int q = 0; q < HALF / 4; q++) {
            float4 bv = b4[q], lv = l4[q];
            rhs[4*q+0] = fmaf(bv.x, xj, rhs[4*q+0]);
            rhs[4*q+1] = fmaf(bv.y, xj, rhs[4*q+1]);
            rhs[4*q+2] = fmaf(bv.z, xj, rhs[4*q+2]);
            rhs[4*q+3] = fmaf(bv.w, xj, rhs[4*q+3]);
            lam[4*q+0] = fmaf(lv.x, xj, lam[4*q+0]);
            lam[4*q+1] = fmaf(lv.y, xj, lam[4*q+1]);
            lam[4*q+2] = fmaf(lv.z, xj, lam[4*q+2]);
            lam[4*q+3] = fmaf(lv.w, xj, lam[4*q+3]);
        }
    }
    for (int k = 0; k < NINT; k++) {
        float zk = sZ[ls][k];
        const float4* t4 = reinterpret_cast<const float4*>(&sTt[k][rb]);
#pragma unroll
        for (int q = 0; q < HALF / 4; q++) {
            float4 tv = t4[q];
            rhs[4*q+0] = fmaf(tv.x, zk, rhs[4*q+0]);
            rhs[4*q+1] = fmaf(tv.y, zk, rhs[4*q+1]);
            rhs[4*q+2] = fmaf(tv.z, zk, rhs[4*q+2]);
            rhs[4*q+3] = fmaf(tv.w, zk, rhs[4*q+3]);
        }
    }

    // ---- Phase 2: dinv, scaled rhs, y0 ----
    float dinv[HALF], y[HALF];
#pragma unroll
    for (int r = 0; r < HALF; r++) {
        dinv[r] = 1.0f / ((1.0f + REGC) - lam[r]);
        rhs[r] *= dinv[r];
        y[r] = rhs[r];
    }

    // ---- Phase 3: Jacobi. Full y vector assembled from lane pair via shfl_xor ----
    for (int it = 0; it < NITER; it++) {
        float ylo[HALF], yhi[HALF];
#pragma unroll
        for (int r = 0; r < HALF; r++) {
            float yo = __shfl_xor_sync(0xFFFFFFFFu, y[r], 1);
            ylo[r] = h ? yo   : y[r];   // y_{r}
            yhi[r] = h ? y[r] : yo;     // y_{16+r}
        }
        float acc[HALF];
#pragma unroll
        for (int r = 0; r < HALF; r++) acc[r] = 0.0f;
#pragma unroll
        for (int j = 0; j < HALF; j++) {
            float yj0 = ylo[j], yj1 = yhi[j];
            const float4* g0 = reinterpret_cast<const float4*>(&sGt[j][rb]);
            const float4* g1 = reinterpret_cast<const float4*>(&sGt[j + HALF][rb]);
#pragma unroll
            for (int q = 0; q < HALF / 4; q++) {
                float4 a = g0[q], b = g1[q];
                acc[4*q+0] = fmaf(a.x, yj0, acc[4*q+0]);
                acc[4*q+1] = fmaf(a.y, yj0, acc[4*q+1]);
                acc[4*q+2] = fmaf(a.z, yj0, acc[4*q+2]);
                acc[4*q+3] = fmaf(a.w, yj0, acc[4*q+3]);
                acc[4*q+0] = fmaf(b.x, yj1, acc[4*q+0]);
                acc[4*q+1] = fmaf(b.y, yj1, acc[4*q+1]);
                acc[4*q+2] = fmaf(b.z, yj1, acc[4*q+2]);
                acc[4*q+3] = fmaf(b.w, yj1, acc[4*q+3]);
            }
        }
#pragma unroll
        for (int r = 0; r < HALF; r++) y[r] = fmaf(dinv[r], acc[r], rhs[r]);
    }

    // ---- Write own half of the output row ----
    float4* O4 = reinterpret_cast<float4*>(out + (size_t)s * NDEP + rb);
#pragma unroll
    for (int q = 0; q < HALF / 4; q++) {
        O4[q] = make_float4(y[4*q+0], y[4*q+1], y[4*q+2], y[4*q+3]);
    }
}

extern "C" void kernel_launch(void* const* d_in, const int* in_sizes, int n_in,
                              void* d_out, int out_size)
{
    const float* X   = (const float*)d_in[0];  // [batch, 64]
    const float* Z   = (const float*)d_in[1];  // [batch, 16]
    const float* Ups = (const float*)d_in[2];  // [32, 1]
    const float* Bm  = (const float*)d_in[3];  // [32, 64]
    const float* Th  = (const float*)d_in[4];  // [32, 16]
    const float* Gm  = (const float*)d_in[5];  // [32, 32]
    const float* Lm  = (const float*)d_in[6];  // [32, 64]
    float* out = (float*)d_out;

    int batch = in_sizes[0] / NIND;
    int nblocks = (batch + SPB - 1) / SPB;
    clefo_kernel<<<nblocks, TPB>>>(X, Z, Ups, Bm, Th, Gm, Lm, out, batch);
}